// round 11
// baseline (speedup 1.0000x reference)
#include <cuda_runtime.h>
#include <cuda_bf16.h>

// Fused separable 15x15 Gaussian blur, fp32 in/out, N x 1024 x 1024.
// R10 = R8 (TX=128, TY=64, 256 thr, f32 smem, 2048 blocks) with phase-1
// hybrid-packed FFMA2:
//  - 5 LDG.128 chunks held as ulonglong2 halves in a union -> every even-
//    start float pair (v[s],v[s+1]) IS 64-bit register u[s/2], zero movs.
//  - odd-j taps (7): 2x FFMA2 each (pairs (o0,o1),(o2,o3), starts 1+j / 3+j
//    both even). even-j taps (8): scalar FFMA. 14 FFMA2 + 32 FFMA + 4 FADD
//    vs 60 FFMA before.
// Phase 2 unchanged: ld.shared.b64 float2 -> fma.rn.f32x2, 2 serial 8-row
// strips x 64 col-pairs.

#define RAD 7
#define KS  15
#define TX  128
#define TY  64
#define HYP 80                  // 78 needed rows padded to 80 (10 iters x 8 rows)
#define NTHREADS 256
#define IMG_W 1024
#define IMG_H 1024

typedef unsigned long long ull;

__device__ __forceinline__ ull pack2(float a, float b) {
    ull r;
    asm("mov.b64 %0, {%1, %2};" : "=l"(r) : "f"(a), "f"(b));
    return r;
}
__device__ __forceinline__ void unpack2(ull p, float& a, float& b) {
    asm("mov.b64 {%0, %1}, %2;" : "=f"(a), "=f"(b) : "l"(p));
}
__device__ __forceinline__ ull ffma2(ull a, ull b, ull c) {
    ull d;
    asm("fma.rn.f32x2 %0, %1, %2, %3;" : "=l"(d) : "l"(a), "l"(b), "l"(c));
    return d;
}
__device__ __forceinline__ ull fmul2(ull a, ull b) {
    ull d;
    asm("mul.rn.f32x2 %0, %1, %2;" : "=l"(d) : "l"(a), "l"(b));
    return d;
}

__global__ void __launch_bounds__(NTHREADS, 5)
gauss15_fused10_kernel(const float* __restrict__ x,
                       const float* __restrict__ sigma_p,
                       const float* __restrict__ gain_p,
                       float* __restrict__ out)
{
    __shared__ alignas(16) float s_hz[HYP * TX];   // 40 KB

    const int tid = threadIdx.x;
    const int x0 = blockIdx.x * TX;
    const int y0 = blockIdx.y * TY;
    const long long plane = (long long)blockIdx.z * (IMG_W * IMG_H);
    const float* img = x + plane;
    float* outp = out + plane;

    // ---- weights ----
    // even-j scalars: we0..we3 = w[0],w[2],w[4],w[6]  (j=8,10,12,14 mirror 6,4,2,0)
    // odd-j packed:   wo0..wo3 = {w1,w1},{w3,w3},{w5,w5},{w7,w7} (9,11,13 mirror)
    const float s = fabsf(sigma_p[0]);
    const float g = gain_p[0];
    const float inv2s2 = 1.0f / (2.0f * s * s);
    float we[4];
    ull wo[4];
#pragma unroll
    for (int m = 0; m < 4; m++) {
        float de = (float)(2 * m - RAD);
        we[m] = __expf(-de * de * inv2s2);
        float dz = (float)(2 * m + 1 - RAD);
        float wod = __expf(-dz * dz * inv2s2);
        wo[m] = pack2(wod, wod);
    }
    // scalar even weight for tap j (j even): index min(j,14-j)/2
#define WE(j) we[(((j) <= 7) ? (j) : (14 - (j))) >> 1]
    // packed odd weight for tap j (j odd): index min(j,14-j)/2
#define WO(j) wo[(((j) <= 7) ? (j) : (14 - (j))) >> 1]

    // ---- phase 1: horizontal conv, direct from global, hybrid packed ----
    // cg = tid & 31 (invariant), r = (tid>>5) + 8*it, it in [0,10).
    {
        const int cg = tid & 31;
        const int r0 = tid >> 5;
        const int gxb = x0 - 8 + cg * 4;
        const float* rowp0 = img + (long long)(y0 - RAD + r0) * IMG_W + gxb;
        float* hzp0 = s_hz + r0 * TX + cg * 4;

        bool cvx[5];
#pragma unroll
        for (int k = 0; k < 5; k++) {
            int gx = gxb + 4 * k;
            cvx[k] = (gx >= 0) && (gx < IMG_W);
        }

#pragma unroll
        for (int it = 0; it < 10; it++) {
            const int gy = y0 - RAD + (r0 + 8 * it);
            const bool rv = ((unsigned)gy < (unsigned)IMG_H);
            const float* rowp = rowp0 + (long long)(8 * it) * IMG_W;

            union {
                ull u[10];       // u[p] = (f[2p], f[2p+1])
                float f[20];
            } v;
#pragma unroll
            for (int k = 0; k < 5; k++) {
                ulonglong2 q = make_ulonglong2(0ull, 0ull);
                if (rv && cvx[k]) q = *(const ulonglong2*)(rowp + 4 * k);
                v.u[2 * k + 0] = q.x;
                v.u[2 * k + 1] = q.y;
            }

            // packed accumulators for odd taps
            ull P01 = 0ull, P23 = 0ull;
#pragma unroll
            for (int j = 1; j < KS; j += 2) {
                ull wp = WO(j);
                P01 = ffma2(wp, v.u[(1 + j) >> 1], P01);   // pair (f[1+j], f[2+j])
                P23 = ffma2(wp, v.u[(3 + j) >> 1], P23);   // pair (f[3+j], f[4+j])
            }
            // scalar accumulators for even taps
            float s0 = 0.f, s1 = 0.f, s2 = 0.f, s3 = 0.f;
#pragma unroll
            for (int j = 0; j < KS; j += 2) {
                float wj = WE(j);
                s0 = fmaf(wj, v.f[1 + j], s0);
                s1 = fmaf(wj, v.f[2 + j], s1);
                s2 = fmaf(wj, v.f[3 + j], s2);
                s3 = fmaf(wj, v.f[4 + j], s3);
            }

            float p0, p1, p2, p3;
            unpack2(P01, p0, p1);
            unpack2(P23, p2, p3);
            *(float4*)(hzp0 + 8 * it * TX) =
                make_float4(s0 + p0, s1 + p1, s2 + p2, s3 + p3);
        }
    }
    __syncthreads();

    // ---- phase 2: vertical conv; 8 strips x 8 rows x 64 col-pairs ----
    {
        const int cp = tid & 63;
        const int ss0 = tid >> 6;

        // full packed weight table for vertical taps
        ull wv[8];
#pragma unroll
        for (int m = 0; m < 4; m++) {
            float e = we[m];
            wv[2 * m] = pack2(e, e);
            wv[2 * m + 1] = wo[m];
        }
#define WV(j) wv[((j) <= 7) ? (j) : (14 - (j))]
        const ull gp = pack2(g, g);

#pragma unroll
        for (int sit = 0; sit < 2; sit++) {
            const int ob = (ss0 + 4 * sit) * 8;

            ull acc[8];
#pragma unroll
            for (int i = 0; i < 8; i++) acc[i] = 0ull;

            const ull* hzbase = (const ull*)(s_hz + ob * TX) + cp;
#pragma unroll
            for (int t = 0; t < KS + 7; t++) {            // hz rows ob .. ob+21
                ull v = hzbase[t * (TX / 2)];
#pragma unroll
                for (int k = 0; k < 8; k++) {
                    if (t >= k && t - k < KS)
                        acc[k] = ffma2(WV(t - k), v, acc[k]);
                }
            }

            float* o = outp + (long long)(y0 + ob) * IMG_W + x0 + cp * 2;
#pragma unroll
            for (int k = 0; k < 8; k++) {
                ull r = fmul2(acc[k], gp);
                float a, b;
                unpack2(r, a, b);
                *(float2*)(o + (long long)k * IMG_W) = make_float2(a, b);
            }
        }
    }
}

extern "C" void kernel_launch(void* const* d_in, const int* in_sizes, int n_in,
                              void* d_out, int out_size)
{
    const float* x     = (const float*)d_in[0];
    const float* sigma = (const float*)d_in[1];
    const float* gain  = (const float*)d_in[2];
    float* out = (float*)d_out;

    int nimg = in_sizes[0] / (IMG_W * IMG_H);

    dim3 grid(IMG_W / TX, IMG_H / TY, nimg);
    gauss15_fused10_kernel<<<grid, NTHREADS>>>(x, sigma, gain, out);
}

// round 13
// speedup vs baseline: 1.1795x; 1.1795x over previous
#include <cuda_runtime.h>
#include <cuda_bf16.h>
#include <cuda_fp16.h>

// Fused separable 15x15 Gaussian blur, fp32 in/out, N x 1024 x 1024.
// R11 = R6 (TY=32, fp16 hz intermediate, 256 thr) tuned for occupancy 6:
//  - __launch_bounds__(256, 6): target <=40 regs, 48 warps/SM.
//  - Phase 1 uses progressive chunk consumption (load 4-float chunk,
//    immediately fold into the 4 accumulators, retire) to cut the live
//    register window from 20+ to ~8.
//  - Phase 2 identical to R6: LDS.32 half2 -> cvt -> fma.rn.f32x2, acc[8],
//    4 strips x 8 rows x 64 col-pairs, all threads active.

#define RAD 7
#define KS  15
#define TX  128
#define TY  32
#define HYP 48                  // 46 needed rows padded to 48 (6 iters x 8 rows)
#define NTHREADS 256
#define IMG_W 1024
#define IMG_H 1024

typedef unsigned long long ull;

__device__ __forceinline__ ull pack2(float a, float b) {
    ull r;
    asm("mov.b64 %0, {%1, %2};" : "=l"(r) : "f"(a), "f"(b));
    return r;
}
__device__ __forceinline__ void unpack2(ull p, float& a, float& b) {
    asm("mov.b64 {%0, %1}, %2;" : "=f"(a), "=f"(b) : "l"(p));
}
__device__ __forceinline__ ull ffma2(ull a, ull b, ull c) {
    ull d;
    asm("fma.rn.f32x2 %0, %1, %2, %3;" : "=l"(d) : "l"(a), "l"(b), "l"(c));
    return d;
}
__device__ __forceinline__ ull fmul2(ull a, ull b) {
    ull d;
    asm("mul.rn.f32x2 %0, %1, %2;" : "=l"(d) : "l"(a), "l"(b));
    return d;
}
// half2 (as u32) -> packed f32x2 in one 64-bit reg
__device__ __forceinline__ ull h2_to_f2(unsigned int h) {
    float lo, hi;
    asm("{.reg .f16 l, h;\n\t"
        " mov.b32 {l, h}, %2;\n\t"
        " cvt.f32.f16 %0, l;\n\t"
        " cvt.f32.f16 %1, h;}"
        : "=f"(lo), "=f"(hi) : "r"(h));
    return pack2(lo, hi);
}

__global__ void __launch_bounds__(NTHREADS, 6)
gauss15_fused11_kernel(const float* __restrict__ x,
                       const float* __restrict__ sigma_p,
                       const float* __restrict__ gain_p,
                       float* __restrict__ out)
{
    __shared__ alignas(16) __half s_hz[HYP * TX];   // 12 KB

    const int tid = threadIdx.x;
    const int x0 = blockIdx.x * TX;
    const int y0 = blockIdx.y * TY;
    const long long plane = (long long)blockIdx.z * (IMG_W * IMG_H);
    const float* img = x + plane;
    float* outp = out + plane;

    // ---- weights: 8 distinct scalars (symmetric) ----
    const float s = fabsf(sigma_p[0]);
    const float g = gain_p[0];
    const float inv2s2 = 1.0f / (2.0f * s * s);
    float ws[8];
#pragma unroll
    for (int j = 0; j < 8; j++) {
        float d = (float)(j - RAD);
        ws[j] = __expf(-d * d * inv2s2);
    }
#define WJ(j) ws[((j) <= 7) ? (j) : (14 - (j))]

    // ---- phase 1: horizontal conv, direct from global ----
    // cg = tid & 31 (invariant), r = (tid>>5) + 8*it, it in [0,6).
    // Progressive consumption: chunk k folded immediately, small live window.
    {
        const int cg = tid & 31;
        const int r0 = tid >> 5;
        const int gxb = x0 - 8 + cg * 4;
        const float* rowp0 = img + (long long)(y0 - RAD + r0) * IMG_W + gxb;
        __half* hzp0 = s_hz + r0 * TX + cg * 4;

        bool cvx[5];
#pragma unroll
        for (int k = 0; k < 5; k++) {
            int gx = gxb + 4 * k;
            cvx[k] = (gx >= 0) && (gx < IMG_W);
        }

#pragma unroll
        for (int it = 0; it < 6; it++) {
            const int gy = y0 - RAD + (r0 + 8 * it);
            const bool rv = ((unsigned)gy < (unsigned)IMG_H);
            const float* rowp = rowp0 + (long long)(8 * it) * IMG_W;

            float a0 = 0.f, a1 = 0.f, a2 = 0.f, a3 = 0.f;
#pragma unroll
            for (int k = 0; k < 5; k++) {
                float4 t = make_float4(0.f, 0.f, 0.f, 0.f);
                if (rv && cvx[k]) t = *(const float4*)(rowp + 4 * k);
                float c[4] = {t.x, t.y, t.z, t.w};
#pragma unroll
                for (int m = 0; m < 4; m++) {
                    const int sgl = 4 * k + m;        // window index
                    // output a consumes tap j = sgl - 1 - a
                    {
                        int j = sgl - 1;
                        if (j >= 0 && j < KS) a0 = fmaf(WJ(j), c[m], a0);
                    }
                    {
                        int j = sgl - 2;
                        if (j >= 0 && j < KS) a1 = fmaf(WJ(j), c[m], a1);
                    }
                    {
                        int j = sgl - 3;
                        if (j >= 0 && j < KS) a2 = fmaf(WJ(j), c[m], a2);
                    }
                    {
                        int j = sgl - 4;
                        if (j >= 0 && j < KS) a3 = fmaf(WJ(j), c[m], a3);
                    }
                }
            }

            __half2 h01 = __floats2half2_rn(a0, a1);
            __half2 h23 = __floats2half2_rn(a2, a3);
            uint2 st;
            st.x = *(unsigned int*)&h01;
            st.y = *(unsigned int*)&h23;
            *(uint2*)(hzp0 + 8 * it * TX) = st;
        }
    }
    __syncthreads();

    // ---- phase 2: vertical conv, 4 strips x 8 rows x 64 col-pairs ----
    {
        const int cp = tid & 63;
        const int ss = tid >> 6;
        const int ob = ss * 8;

        ull wv[8];
#pragma unroll
        for (int j = 0; j < 8; j++) wv[j] = pack2(ws[j], ws[j]);
#define WV(j) wv[((j) <= 7) ? (j) : (14 - (j))]

        ull acc[8];
#pragma unroll
        for (int i = 0; i < 8; i++) acc[i] = 0ull;

        const unsigned int* hzbase =
            (const unsigned int*)(s_hz + ob * TX) + cp;   // half2 units, row stride TX/2
#pragma unroll
        for (int t = 0; t < KS + 7; t++) {                // hz rows ob .. ob+21
            ull v = h2_to_f2(hzbase[t * (TX / 2)]);
#pragma unroll
            for (int k = 0; k < 8; k++) {
                if (t >= k && t - k < KS)
                    acc[k] = ffma2(WV(t - k), v, acc[k]);
            }
        }

        const ull gp = pack2(g, g);
        float* o = outp + (long long)(y0 + ob) * IMG_W + x0 + cp * 2;
#pragma unroll
        for (int k = 0; k < 8; k++) {
            ull r = fmul2(acc[k], gp);
            float a, b;
            unpack2(r, a, b);
            *(float2*)(o + (long long)k * IMG_W) = make_float2(a, b);
        }
    }
}

extern "C" void kernel_launch(void* const* d_in, const int* in_sizes, int n_in,
                              void* d_out, int out_size)
{
    const float* x     = (const float*)d_in[0];
    const float* sigma = (const float*)d_in[1];
    const float* gain  = (const float*)d_in[2];
    float* out = (float*)d_out;

    int nimg = in_sizes[0] / (IMG_W * IMG_H);

    dim3 grid(IMG_W / TX, IMG_H / TY, nimg);
    gauss15_fused11_kernel<<<grid, NTHREADS>>>(x, sigma, gain, out);
}

// round 14
// speedup vs baseline: 1.3724x; 1.1635x over previous
#include <cuda_runtime.h>
#include <cuda_bf16.h>
#include <cuda_fp16.h>

// Fused separable 15x15 Gaussian blur, fp32 in/out, N x 1024 x 1024.
// R12: tall tile 64(x) x 128(y) -> y-halo redundancy 1.125x (was 1.5x at TY=32).
//  Phase 1: 4-wide items, 5 predicated LDG.128 direct from global, 60 scalar
//           FMA, fp16 results (uint2 STS). 9 iters x 16 rows = 144 hz rows.
//  Phase 2: R6/R8 scheme at TX=64: 16 strips x 8 rows x 32 col-pairs,
//           2 serial strips/thread, LDS.32 half2 -> f32x2 FFMA2, fp32 acc.
// 256 threads, grid (16, 8, 16) = 2048 blocks, smem 18.4 KB, occ target 5.

#define RAD 7
#define KS  15
#define TX  64
#define TY  128
#define HYP 144                 // 142 needed rows padded to 144 (9 iters x 16 rows)
#define NTHREADS 256
#define IMG_W 1024
#define IMG_H 1024

typedef unsigned long long ull;

__device__ __forceinline__ ull pack2(float a, float b) {
    ull r;
    asm("mov.b64 %0, {%1, %2};" : "=l"(r) : "f"(a), "f"(b));
    return r;
}
__device__ __forceinline__ void unpack2(ull p, float& a, float& b) {
    asm("mov.b64 {%0, %1}, %2;" : "=f"(a), "=f"(b) : "l"(p));
}
__device__ __forceinline__ ull ffma2(ull a, ull b, ull c) {
    ull d;
    asm("fma.rn.f32x2 %0, %1, %2, %3;" : "=l"(d) : "l"(a), "l"(b), "l"(c));
    return d;
}
__device__ __forceinline__ ull fmul2(ull a, ull b) {
    ull d;
    asm("mul.rn.f32x2 %0, %1, %2;" : "=l"(d) : "l"(a), "l"(b));
    return d;
}
// half2 (as u32) -> packed f32x2 in one 64-bit reg
__device__ __forceinline__ ull h2_to_f2(unsigned int h) {
    float lo, hi;
    asm("{.reg .f16 l, h;\n\t"
        " mov.b32 {l, h}, %2;\n\t"
        " cvt.f32.f16 %0, l;\n\t"
        " cvt.f32.f16 %1, h;}"
        : "=f"(lo), "=f"(hi) : "r"(h));
    return pack2(lo, hi);
}

__global__ void __launch_bounds__(NTHREADS, 5)
gauss15_fused12_kernel(const float* __restrict__ x,
                       const float* __restrict__ sigma_p,
                       const float* __restrict__ gain_p,
                       float* __restrict__ out)
{
    __shared__ alignas(16) __half s_hz[HYP * TX];   // 18.4 KB

    const int tid = threadIdx.x;
    const int x0 = blockIdx.x * TX;
    const int y0 = blockIdx.y * TY;
    const long long plane = (long long)blockIdx.z * (IMG_W * IMG_H);
    const float* img = x + plane;
    float* outp = out + plane;

    // ---- weights: 8 distinct scalars (symmetric) ----
    const float s = fabsf(sigma_p[0]);
    const float g = gain_p[0];
    const float inv2s2 = 1.0f / (2.0f * s * s);
    float ws[8];
#pragma unroll
    for (int j = 0; j < 8; j++) {
        float d = (float)(j - RAD);
        ws[j] = __expf(-d * d * inv2s2);
    }
#define WJ(j) ws[((j) <= 7) ? (j) : (14 - (j))]

    // ---- phase 1: horizontal conv, direct from global ----
    // cg = tid & 15 (invariant; cols x0+4cg..+3), r = (tid>>4) + 16*it, it in [0,9).
    {
        const int cg = tid & 15;
        const int r0 = tid >> 4;
        const int gxb = x0 - 8 + cg * 4;
        const float* rowp0 = img + (long long)(y0 - RAD + r0) * IMG_W + gxb;
        __half* hzp0 = s_hz + r0 * TX + cg * 4;

        bool cvx[5];
#pragma unroll
        for (int k = 0; k < 5; k++) {
            int gx = gxb + 4 * k;
            cvx[k] = (gx >= 0) && (gx < IMG_W);
        }

#pragma unroll
        for (int it = 0; it < 9; it++) {
            const int gy = y0 - RAD + (r0 + 16 * it);
            const bool rv = ((unsigned)gy < (unsigned)IMG_H);
            const float* rowp = rowp0 + (long long)(16 * it) * IMG_W;

            float v[20];
#pragma unroll
            for (int k = 0; k < 5; k++) {
                float4 t = make_float4(0.f, 0.f, 0.f, 0.f);
                if (rv && cvx[k]) t = *(const float4*)(rowp + 4 * k);
                v[4 * k + 0] = t.x; v[4 * k + 1] = t.y;
                v[4 * k + 2] = t.z; v[4 * k + 3] = t.w;
            }
            float o0 = 0.f, o1 = 0.f, o2 = 0.f, o3 = 0.f;
#pragma unroll
            for (int j = 0; j < KS; j++) {
                float wj = WJ(j);
                o0 = fmaf(wj, v[1 + j], o0);
                o1 = fmaf(wj, v[2 + j], o1);
                o2 = fmaf(wj, v[3 + j], o2);
                o3 = fmaf(wj, v[4 + j], o3);
            }
            __half2 h01 = __floats2half2_rn(o0, o1);
            __half2 h23 = __floats2half2_rn(o2, o3);
            uint2 st;
            st.x = *(unsigned int*)&h01;
            st.y = *(unsigned int*)&h23;
            *(uint2*)(hzp0 + 16 * it * TX) = st;
        }
    }
    __syncthreads();

    // ---- phase 2: vertical conv, 16 strips x 8 rows x 32 col-pairs ----
    // cp = tid & 31 (cols 2cp, 2cp+1), ss0 = tid >> 5 in [0,8);
    // each thread does strips ss0 and ss0+8 serially.
    {
        const int cp = tid & 31;
        const int ss0 = tid >> 5;

        ull wv[8];
#pragma unroll
        for (int j = 0; j < 8; j++) wv[j] = pack2(ws[j], ws[j]);
#define WV(j) wv[((j) <= 7) ? (j) : (14 - (j))]
        const ull gp = pack2(g, g);

#pragma unroll
        for (int sit = 0; sit < 2; sit++) {
            const int ob = (ss0 + 8 * sit) * 8;

            ull acc[8];
#pragma unroll
            for (int i = 0; i < 8; i++) acc[i] = 0ull;

            const unsigned int* hzbase =
                (const unsigned int*)(s_hz + ob * TX) + cp;  // half2 units, row stride TX/2
#pragma unroll
            for (int t = 0; t < KS + 7; t++) {               // hz rows ob .. ob+21
                ull v = h2_to_f2(hzbase[t * (TX / 2)]);
#pragma unroll
                for (int k = 0; k < 8; k++) {
                    if (t >= k && t - k < KS)
                        acc[k] = ffma2(WV(t - k), v, acc[k]);
                }
            }

            float* o = outp + (long long)(y0 + ob) * IMG_W + x0 + cp * 2;
#pragma unroll
            for (int k = 0; k < 8; k++) {
                ull r = fmul2(acc[k], gp);
                float a, b;
                unpack2(r, a, b);
                *(float2*)(o + (long long)k * IMG_W) = make_float2(a, b);
            }
        }
    }
}

extern "C" void kernel_launch(void* const* d_in, const int* in_sizes, int n_in,
                              void* d_out, int out_size)
{
    const float* x     = (const float*)d_in[0];
    const float* sigma = (const float*)d_in[1];
    const float* gain  = (const float*)d_in[2];
    float* out = (float*)d_out;

    int nimg = in_sizes[0] / (IMG_W * IMG_H);

    dim3 grid(IMG_W / TX, IMG_H / TY, nimg);
    gauss15_fused12_kernel<<<grid, NTHREADS>>>(x, sigma, gain, out);
}